// round 8
// baseline (speedup 1.0000x reference)
#include <cuda_runtime.h>
#include <cuda_fp16.h>
#include <math_constants.h>
#include <cstdint>

#define N_NODES 50000
#define F_IN    256
#define H_DIM   128
#define C_DIM   64
#define E_MAX   1600000
#define NEG_SLOPE 0.2f
#define EPS_F 1e-16f

// ---------------- scratch (device globals; no allocation allowed) ----------
__device__ __half g_xl1h[N_NODES * H_DIM];   // fp16 source-side features (layer1)
__device__ float  g_xr1 [N_NODES * H_DIM];
__device__ float  g_h   [N_NODES * H_DIM];   // layer1 output / layer2 input
__device__ __half g_xl2h[N_NODES * C_DIM];
__device__ float  g_xr2 [N_NODES * C_DIM];
__device__ int    g_deg[N_NODES];
__device__ int    g_rowptr[N_NODES + 1];
__device__ int    g_wp [N_NODES];
__device__ int    g_csrc[E_MAX];             // src ids grouped by dst

// ==================== small asm helpers =====================================
__device__ __forceinline__ uint32_t smem_to_u32(const void* p) {
    uint32_t a;
    asm("{ .reg .u64 t; cvta.to.shared.u64 t, %1; cvt.u32.u64 %0, t; }"
        : "=r"(a) : "l"(p));
    return a;
}
__device__ __forceinline__ void sts64(uint32_t a, uint32_t v0, uint32_t v1) {
    asm volatile("st.shared.v2.b32 [%0], {%1, %2};" :: "r"(a), "r"(v0), "r"(v1) : "memory");
}
__device__ __forceinline__ void ldsm_x4(uint32_t* r, uint32_t addr) {
    asm volatile("ldmatrix.sync.aligned.m8n8.x4.shared.b16 {%0,%1,%2,%3}, [%4];"
        : "=r"(r[0]), "=r"(r[1]), "=r"(r[2]), "=r"(r[3]) : "r"(addr));
}
__device__ __forceinline__ void ldsm_x4_trans(uint32_t* r, uint32_t addr) {
    asm volatile("ldmatrix.sync.aligned.m8n8.x4.trans.shared.b16 {%0,%1,%2,%3}, [%4];"
        : "=r"(r[0]), "=r"(r[1]), "=r"(r[2]), "=r"(r[3]) : "r"(addr));
}
__device__ __forceinline__ void mma16816h(float* c, const uint32_t* a, const uint32_t* b) {
    asm volatile(
        "mma.sync.aligned.m16n8k16.row.col.f32.f16.f16.f32 "
        "{%0,%1,%2,%3}, {%4,%5,%6,%7}, {%8,%9}, {%0,%1,%2,%3};"
        : "+f"(c[0]), "+f"(c[1]), "+f"(c[2]), "+f"(c[3])
        : "r"(a[0]), "r"(a[1]), "r"(a[2]), "r"(a[3]), "r"(b[0]), "r"(b[1]));
}

// ==================== fp16 tensor-core GEMM (mma.sync + ldmatrix) ===========
template<int KFULL, int NHALF>
__global__ __launch_bounds__(256, 2)
void gemm_mma_fp16(const float* __restrict__ A,
                   const float* __restrict__ Wl, const float* __restrict__ Wr,
                   __half* __restrict__ Hl, float* __restrict__ Cr, int M) {
    constexpr int NC = KFULL / 64;
    constexpr uint32_t BOFF = 18432;             // 128*144
    constexpr uint32_t BUF  = 18432 + 17408;     // + 64*272 = 35840

    extern __shared__ char smem[];
    const uint32_t sb = smem_to_u32(smem);

    const int tid = threadIdx.x;
    const int wid = tid >> 5;
    const int l   = tid & 31;
    const int wr  = wid >> 2;
    const int wc  = wid & 3;
    const int m0  = blockIdx.x * 128;
    const int z   = blockIdx.z;

    float acc[4][4][4];
    #pragma unroll
    for (int i = 0; i < 4; i++)
        #pragma unroll
        for (int j = 0; j < 4; j++)
            #pragma unroll
            for (int q = 0; q < 4; q++) acc[i][j][q] = 0.0f;

    auto fillA = [&](int c, uint32_t bufb) {
        const int k0 = c * 64;
        #pragma unroll
        for (int i = 0; i < 8; i++) {
            int fid = tid + i * 256;
            int r   = fid >> 4;
            int c4  = fid & 15;
            float4 v = make_float4(0.f, 0.f, 0.f, 0.f);
            int gr = m0 + r;
            if (gr < M)
                v = *(const float4*)(A + (size_t)gr * KFULL + k0 + c4 * 4);
            __half2 h01 = __floats2half2_rn(v.x, v.y);
            __half2 h23 = __floats2half2_rn(v.z, v.w);
            sts64(bufb + (uint32_t)r * 144 + (uint32_t)c4 * 8,
                  *(uint32_t*)&h01, *(uint32_t*)&h23);
        }
    };

    auto fillB = [&](int c, uint32_t bufb) {
        const int k0 = c * 64;
        #pragma unroll
        for (int i = 0; i < 8; i++) {
            int fid = tid + i * 256;
            int k   = fid >> 5;
            int n0  = (fid & 31) * 4;
            int gc  = z * 128 + n0;
            const float* Wp = (gc < NHALF) ? Wl : Wr;
            int col = (gc < NHALF) ? gc : gc - NHALF;
            float4 v = *(const float4*)(Wp + (size_t)(k0 + k) * NHALF + col);
            __half2 h01 = __floats2half2_rn(v.x, v.y);
            __half2 h23 = __floats2half2_rn(v.z, v.w);
            sts64(bufb + BOFF + (uint32_t)k * 272 + (uint32_t)n0 * 2,
                  *(uint32_t*)&h01, *(uint32_t*)&h23);
        }
    };

    auto compute = [&](uint32_t bufb) {
        const uint32_t aLane = bufb + ((uint32_t)(wr * 64 + (l & 15))) * 144
                             + (uint32_t)((l >> 4) & 1) * 16;
        const uint32_t bLane = bufb + BOFF + (uint32_t)(l & 15) * 272
                             + (uint32_t)((l >> 4) & 1) * 16
                             + (uint32_t)(wc * 32) * 2;
        #pragma unroll
        for (int ks = 0; ks < 4; ks++) {
            uint32_t af[4][4], bf[2][4];
            #pragma unroll
            for (int mf = 0; mf < 4; mf++)
                ldsm_x4(af[mf], aLane + (uint32_t)mf * 2304 + (uint32_t)ks * 32);
            #pragma unroll
            for (int p = 0; p < 2; p++)
                ldsm_x4_trans(bf[p], bLane + (uint32_t)ks * 4352 + (uint32_t)p * 32);
            #pragma unroll
            for (int mf = 0; mf < 4; mf++)
                #pragma unroll
                for (int nf = 0; nf < 4; nf++)
                    mma16816h(acc[mf][nf], af[mf], &bf[nf >> 1][(nf & 1) * 2]);
        }
    };

    fillA(0, sb); fillB(0, sb);
    __syncthreads();
    #pragma unroll
    for (int c = 0; c < NC; c++) {
        uint32_t cur = sb + (uint32_t)(c & 1) * BUF;
        if (c + 1 < NC) {
            uint32_t nxt = sb + (uint32_t)((c + 1) & 1) * BUF;
            fillA(c + 1, nxt); fillB(c + 1, nxt);
        }
        compute(cur);
        __syncthreads();
    }

    #pragma unroll
    for (int mf = 0; mf < 4; mf++) {
        int r0 = m0 + wr * 64 + mf * 16 + (l >> 2);
        #pragma unroll
        for (int nf = 0; nf < 4; nf++) {
            int colL = wc * 32 + nf * 8 + (l & 3) * 2;
            int gc = z * 128 + colL;
            bool selL = gc < NHALF;
            int ch = selL ? gc : gc - NHALF;
            if (r0 < M) {
                if (selL)
                    *(__half2*)(Hl + (size_t)r0 * NHALF + ch) =
                        __floats2half2_rn(acc[mf][nf][0], acc[mf][nf][1]);
                else
                    *(float2*)(Cr + (size_t)r0 * NHALF + ch) =
                        make_float2(acc[mf][nf][0], acc[mf][nf][1]);
            }
            if (r0 + 8 < M) {
                if (selL)
                    *(__half2*)(Hl + (size_t)(r0 + 8) * NHALF + ch) =
                        __floats2half2_rn(acc[mf][nf][2], acc[mf][nf][3]);
                else
                    *(float2*)(Cr + (size_t)(r0 + 8) * NHALF + ch) =
                        make_float2(acc[mf][nf][2], acc[mf][nf][3]);
            }
        }
    }
}

// ==================== CSR build ==============================================
__global__ void zero_deg_kernel() {
    int i = blockIdx.x * blockDim.x + threadIdx.x;
    if (i < N_NODES) g_deg[i] = 0;
}

__global__ void hist_kernel(const int* __restrict__ dst, int E) {
    int i = (blockIdx.x * blockDim.x + threadIdx.x) * 4;
    if (i >= E) return;
    if (i + 4 <= E) {
        int4 d = *(const int4*)(dst + i);
        atomicAdd(&g_deg[d.x], 1);
        atomicAdd(&g_deg[d.y], 1);
        atomicAdd(&g_deg[d.z], 1);
        atomicAdd(&g_deg[d.w], 1);
    } else {
        for (int e = i; e < E; e++) atomicAdd(&g_deg[dst[e]], 1);
    }
}

__global__ void scan_kernel(int E) {
    __shared__ int wsums[32];
    __shared__ int carry_sh;
    const int lane = threadIdx.x & 31;
    const int w    = threadIdx.x >> 5;
    if (threadIdx.x == 0) carry_sh = 0;
    __syncthreads();
    for (int base = 0; base < N_NODES; base += 1024) {
        int i = base + (int)threadIdx.x;
        int v = (i < N_NODES) ? g_deg[i] : 0;
        int x = v;
        #pragma unroll
        for (int o = 1; o < 32; o <<= 1) {
            int t = __shfl_up_sync(0xFFFFFFFFu, x, o);
            if (lane >= o) x += t;
        }
        if (lane == 31) wsums[w] = x;
        __syncthreads();
        if (w == 0) {
            int y = wsums[lane];
            #pragma unroll
            for (int o = 1; o < 32; o <<= 1) {
                int u = __shfl_up_sync(0xFFFFFFFFu, y, o);
                if (lane >= o) y += u;
            }
            wsums[lane] = y;
        }
        __syncthreads();
        int warpoff = (w == 0) ? 0 : wsums[w - 1];
        int incl = x + warpoff + carry_sh;
        if (i < N_NODES) { g_rowptr[i] = incl - v; g_wp[i] = incl - v; }
        __syncthreads();
        if (threadIdx.x == 1023) carry_sh = incl;
        __syncthreads();
    }
    if (threadIdx.x == 0) g_rowptr[N_NODES] = E;
}

__global__ void scatter_kernel(const int* __restrict__ src, const int* __restrict__ dst, int E) {
    int i = (blockIdx.x * blockDim.x + threadIdx.x) * 4;
    if (i >= E) return;
    if (i + 4 <= E) {
        int4 s = *(const int4*)(src + i);
        int4 d = *(const int4*)(dst + i);
        int p0 = atomicAdd(&g_wp[d.x], 1);
        int p1 = atomicAdd(&g_wp[d.y], 1);
        int p2 = atomicAdd(&g_wp[d.z], 1);
        int p3 = atomicAdd(&g_wp[d.w], 1);
        g_csrc[p0] = s.x; g_csrc[p1] = s.y; g_csrc[p2] = s.z; g_csrc[p3] = s.w;
    } else {
        for (int e = i; e < E; e++) {
            int pos = atomicAdd(&g_wp[dst[e]], 1);
            g_csrc[pos] = src[e];
        }
    }
}

// ==================== fused GATv2 edge phase ==================================
// Sub-warp groups: F/8 lanes per edge, 8 features per lane (uint4 load),
// 4 edges in flight per group (8/warp F=128, 16/warp F=64).
template<int F, bool RELU>
__global__ void gat_aggregate_kernel(const __half* __restrict__ xl,
                                     const float* __restrict__ xr,
                                     const float* __restrict__ att,
                                     const float* __restrict__ bias,
                                     float* __restrict__ out) {
    constexpr int GS = F / 8;
    constexpr int NG = 32 / GS;
    int n    = (blockIdx.x * blockDim.x + threadIdx.x) >> 5;
    int lane = threadIdx.x & 31;
    if (n >= N_NODES) return;
    const int gid = lane / GS;
    const int f0  = (lane % GS) * 8;

    float xrv[8], attv[8], acc[8];
    {
        float4 xa = *(const float4*)(xr + (size_t)n * F + f0);
        float4 xb = *(const float4*)(xr + (size_t)n * F + f0 + 4);
        float4 aa = *(const float4*)(att + f0);
        float4 ab = *(const float4*)(att + f0 + 4);
        xrv[0]=xa.x; xrv[1]=xa.y; xrv[2]=xa.z; xrv[3]=xa.w;
        xrv[4]=xb.x; xrv[5]=xb.y; xrv[6]=xb.z; xrv[7]=xb.w;
        attv[0]=aa.x; attv[1]=aa.y; attv[2]=aa.z; attv[3]=aa.w;
        attv[4]=ab.x; attv[5]=ab.y; attv[6]=ab.z; attv[7]=ab.w;
    }
    #pragma unroll
    for (int k = 0; k < 8; k++) acc[k] = 0.0f;
    float s = 0.0f;

    const int start = g_rowptr[n];
    const int end   = g_rowptr[n + 1];

    auto unpack = [](uint4 u, float* v) {
        float2 a = __half22float2(*(const __half2*)&u.x);
        float2 b = __half22float2(*(const __half2*)&u.y);
        float2 c = __half22float2(*(const __half2*)&u.z);
        float2 d = __half22float2(*(const __half2*)&u.w);
        v[0] = a.x; v[1] = a.y; v[2] = b.x; v[3] = b.y;
        v[4] = c.x; v[5] = c.y; v[6] = d.x; v[7] = d.y;
    };

    for (int base = start; base < end; base += 32) {
        int myid = (base + lane < end) ? g_csrc[base + lane] : 0;
        int cnt  = min(32, end - base);
        for (int j = 0; j < cnt; j += 4 * NG) {
            uint4 u[4];
            bool act[4];
            #pragma unroll
            for (int q = 0; q < 4; q++) {
                int iq = j + 4 * gid + q;
                act[q] = iq < cnt;
                int sn = __shfl_sync(0xFFFFFFFFu, myid, min(iq, cnt - 1));
                u[q] = *(const uint4*)(xl + (size_t)sn * F + f0);
            }
            float v[4][8], p[4];
            #pragma unroll
            for (int q = 0; q < 4; q++) {
                unpack(u[q], v[q]);
                float pq = 0.0f;
                #pragma unroll
                for (int k = 0; k < 8; k++) {
                    float z = v[q][k] + xrv[k];
                    float lz = z > 0.0f ? z : NEG_SLOPE * z;
                    pq = fmaf(attv[k], lz, pq);
                }
                p[q] = pq;
            }
            #pragma unroll
            for (int o = GS / 2; o > 0; o >>= 1) {
                #pragma unroll
                for (int q = 0; q < 4; q++)
                    p[q] += __shfl_xor_sync(0xFFFFFFFFu, p[q], o);
            }
            float e[4];
            #pragma unroll
            for (int q = 0; q < 4; q++)
                e[q] = act[q] ? __expf(p[q]) : 0.0f;
            s += (e[0] + e[1]) + (e[2] + e[3]);
            #pragma unroll
            for (int k = 0; k < 8; k++)
                acc[k] = fmaf(e[0], v[0][k],
                          fmaf(e[1], v[1][k],
                           fmaf(e[2], v[2][k],
                            fmaf(e[3], v[3][k], acc[k]))));
        }
    }

    #pragma unroll
    for (int o = GS; o < 32; o <<= 1) {
        s += __shfl_xor_sync(0xFFFFFFFFu, s, o);
        #pragma unroll
        for (int k = 0; k < 8; k++)
            acc[k] += __shfl_xor_sync(0xFFFFFFFFu, acc[k], o);
    }

    if (gid == 0) {
        float inv = 1.0f / (s + EPS_F);
        float4 ba = *(const float4*)(bias + f0);
        float4 bb = *(const float4*)(bias + f0 + 4);
        float bv[8] = {ba.x, ba.y, ba.z, ba.w, bb.x, bb.y, bb.z, bb.w};
        float o0[8];
        #pragma unroll
        for (int k = 0; k < 8; k++) {
            float v = acc[k] * inv + bv[k];
            o0[k] = RELU ? (v > 0.0f ? v : 0.0f) : v;
        }
        float* dp = out + (size_t)n * F + f0;
        *(float4*)(dp)     = make_float4(o0[0], o0[1], o0[2], o0[3]);
        *(float4*)(dp + 4) = make_float4(o0[4], o0[5], o0[6], o0[7]);
    }
}

// ==================== launch =================================================
extern "C" void kernel_launch(void* const* d_in, const int* in_sizes, int n_in,
                              void* d_out, int out_size) {
    const float* x    = (const float*)d_in[0];
    const int*   ei   = (const int*)  d_in[1];
    const float* Wl1  = (const float*)d_in[2];
    const float* Wr1  = (const float*)d_in[3];
    const float* att1 = (const float*)d_in[4];
    const float* b1   = (const float*)d_in[5];
    const float* Wl2  = (const float*)d_in[6];
    const float* Wr2  = (const float*)d_in[7];
    const float* att2 = (const float*)d_in[8];
    const float* b2   = (const float*)d_in[9];
    float* out = (float*)d_out;

    const int E = in_sizes[1] / 2;
    const int* src = ei;
    const int* dst = ei + E;

    __half *p_xl1h, *p_xl2h;
    float *p_xr1, *p_h, *p_xr2;
    cudaGetSymbolAddress((void**)&p_xl1h, g_xl1h);
    cudaGetSymbolAddress((void**)&p_xr1,  g_xr1);
    cudaGetSymbolAddress((void**)&p_h,    g_h);
    cudaGetSymbolAddress((void**)&p_xl2h, g_xl2h);
    cudaGetSymbolAddress((void**)&p_xr2,  g_xr2);

    const int SMEM = 2 * 35840;
    cudaFuncSetAttribute(gemm_mma_fp16<F_IN,  H_DIM>,
                         cudaFuncAttributeMaxDynamicSharedMemorySize, SMEM);
    cudaFuncSetAttribute(gemm_mma_fp16<H_DIM, C_DIM>,
                         cudaFuncAttributeMaxDynamicSharedMemorySize, SMEM);

    const int TILES = (N_NODES + 127) / 128;
    const int Q4 = (E + 3) / 4;

    // ---- CSR build ----
    zero_deg_kernel<<<(N_NODES + 255) / 256, 256>>>();
    hist_kernel<<<(Q4 + 255) / 256, 256>>>(dst, E);
    scan_kernel<<<1, 1024>>>(E);
    scatter_kernel<<<(Q4 + 255) / 256, 256>>>(src, dst, E);

    // ---- layer 1 ----
    {
        dim3 grid(TILES, 1, 2);
        gemm_mma_fp16<F_IN, H_DIM><<<grid, 256, SMEM>>>(x, Wl1, Wr1, p_xl1h, p_xr1, N_NODES);
    }
    gat_aggregate_kernel<128, true><<<(N_NODES + 7) / 8, 256>>>(
        p_xl1h, p_xr1, att1, b1, p_h);

    // ---- layer 2 ----
    {
        dim3 grid(TILES, 1, 1);
        gemm_mma_fp16<H_DIM, C_DIM><<<grid, 256, SMEM>>>(p_h, Wl2, Wr2, p_xl2h, p_xr2, N_NODES);
    }
    gat_aggregate_kernel<64, false><<<(N_NODES + 7) / 8, 256>>>(
        p_xl2h, p_xr2, att2, b2, out);
}

// round 9
// speedup vs baseline: 1.2717x; 1.2717x over previous
#include <cuda_runtime.h>
#include <cuda_fp16.h>
#include <math_constants.h>
#include <cstdint>

#define N_NODES 50000
#define F_IN    256
#define H_DIM   128
#define C_DIM   64
#define E_MAX   1600000
#define NEG_SLOPE 0.2f
#define EPS_F 1e-16f

// ---------------- scratch (device globals; no allocation allowed) ----------
__device__ __half g_xl1h[N_NODES * H_DIM];   // fp16 source-side features (layer1)
__device__ float  g_xr1 [N_NODES * H_DIM];
__device__ float  g_h   [N_NODES * H_DIM];   // layer1 output / layer2 input
__device__ __half g_xl2h[N_NODES * C_DIM];
__device__ float  g_xr2 [N_NODES * C_DIM];
__device__ int    g_deg[N_NODES];
__device__ int    g_rowptr[N_NODES + 1];
__device__ int    g_wp [N_NODES];
__device__ int    g_csrc[E_MAX];             // src ids grouped by dst

// ==================== small asm helpers =====================================
__device__ __forceinline__ uint32_t smem_to_u32(const void* p) {
    uint32_t a;
    asm("{ .reg .u64 t; cvta.to.shared.u64 t, %1; cvt.u32.u64 %0, t; }"
        : "=r"(a) : "l"(p));
    return a;
}
__device__ __forceinline__ void sts64(uint32_t a, uint32_t v0, uint32_t v1) {
    asm volatile("st.shared.v2.b32 [%0], {%1, %2};" :: "r"(a), "r"(v0), "r"(v1) : "memory");
}
__device__ __forceinline__ void ldsm_x4(uint32_t* r, uint32_t addr) {
    asm volatile("ldmatrix.sync.aligned.m8n8.x4.shared.b16 {%0,%1,%2,%3}, [%4];"
        : "=r"(r[0]), "=r"(r[1]), "=r"(r[2]), "=r"(r[3]) : "r"(addr));
}
__device__ __forceinline__ void ldsm_x4_trans(uint32_t* r, uint32_t addr) {
    asm volatile("ldmatrix.sync.aligned.m8n8.x4.trans.shared.b16 {%0,%1,%2,%3}, [%4];"
        : "=r"(r[0]), "=r"(r[1]), "=r"(r[2]), "=r"(r[3]) : "r"(addr));
}
__device__ __forceinline__ void mma16816h(float* c, const uint32_t* a, const uint32_t* b) {
    asm volatile(
        "mma.sync.aligned.m16n8k16.row.col.f32.f16.f16.f32 "
        "{%0,%1,%2,%3}, {%4,%5,%6,%7}, {%8,%9}, {%0,%1,%2,%3};"
        : "+f"(c[0]), "+f"(c[1]), "+f"(c[2]), "+f"(c[3])
        : "r"(a[0]), "r"(a[1]), "r"(a[2]), "r"(a[3]), "r"(b[0]), "r"(b[1]));
}

// ==================== fp16 tensor-core GEMM (mma.sync + ldmatrix) ===========
// z in {0,1}: GEMM over fused [Wl | Wr] N-halves.
// If HIST: z == 2 blocks instead run the dst-degree histogram (overlapped).
template<int KFULL, int NHALF, bool HIST>
__global__ __launch_bounds__(256, 2)
void gemm_mma_fp16(const float* __restrict__ A,
                   const float* __restrict__ Wl, const float* __restrict__ Wr,
                   __half* __restrict__ Hl, float* __restrict__ Cr, int M,
                   const int* __restrict__ hdst, int E) {
    constexpr int NC = KFULL / 64;
    constexpr uint32_t BOFF = 18432;             // 128*144
    constexpr uint32_t BUF  = 18432 + 17408;     // + 64*272 = 35840

    const int tid = threadIdx.x;
    const int z   = blockIdx.z;

    if (HIST && z == 2) {
        // grid-stride histogram over edge quads; never touches smem
        const int Q4 = (E + 3) >> 2;
        const int nthr = gridDim.x * blockDim.x;
        for (int q = blockIdx.x * blockDim.x + tid; q < Q4; q += nthr) {
            int i = q * 4;
            if (i + 4 <= E) {
                int4 d = *(const int4*)(hdst + i);
                atomicAdd(&g_deg[d.x], 1);
                atomicAdd(&g_deg[d.y], 1);
                atomicAdd(&g_deg[d.z], 1);
                atomicAdd(&g_deg[d.w], 1);
            } else {
                for (int e = i; e < E; e++) atomicAdd(&g_deg[hdst[e]], 1);
            }
        }
        return;
    }

    extern __shared__ char smem[];
    const uint32_t sb = smem_to_u32(smem);

    const int wid = tid >> 5;
    const int l   = tid & 31;
    const int wr  = wid >> 2;
    const int wc  = wid & 3;
    const int m0  = blockIdx.x * 128;

    float acc[4][4][4];
    #pragma unroll
    for (int i = 0; i < 4; i++)
        #pragma unroll
        for (int j = 0; j < 4; j++)
            #pragma unroll
            for (int q = 0; q < 4; q++) acc[i][j][q] = 0.0f;

    auto fillA = [&](int c, uint32_t bufb) {
        const int k0 = c * 64;
        #pragma unroll
        for (int i = 0; i < 8; i++) {
            int fid = tid + i * 256;
            int r   = fid >> 4;
            int c4  = fid & 15;
            float4 v = make_float4(0.f, 0.f, 0.f, 0.f);
            int gr = m0 + r;
            if (gr < M)
                v = *(const float4*)(A + (size_t)gr * KFULL + k0 + c4 * 4);
            __half2 h01 = __floats2half2_rn(v.x, v.y);
            __half2 h23 = __floats2half2_rn(v.z, v.w);
            sts64(bufb + (uint32_t)r * 144 + (uint32_t)c4 * 8,
                  *(uint32_t*)&h01, *(uint32_t*)&h23);
        }
    };

    auto fillB = [&](int c, uint32_t bufb) {
        const int k0 = c * 64;
        #pragma unroll
        for (int i = 0; i < 8; i++) {
            int fid = tid + i * 256;
            int k   = fid >> 5;
            int n0  = (fid & 31) * 4;
            int gc  = z * 128 + n0;
            const float* Wp = (gc < NHALF) ? Wl : Wr;
            int col = (gc < NHALF) ? gc : gc - NHALF;
            float4 v = *(const float4*)(Wp + (size_t)(k0 + k) * NHALF + col);
            __half2 h01 = __floats2half2_rn(v.x, v.y);
            __half2 h23 = __floats2half2_rn(v.z, v.w);
            sts64(bufb + BOFF + (uint32_t)k * 272 + (uint32_t)n0 * 2,
                  *(uint32_t*)&h01, *(uint32_t*)&h23);
        }
    };

    auto compute = [&](uint32_t bufb) {
        const uint32_t aLane = bufb + ((uint32_t)(wr * 64 + (l & 15))) * 144
                             + (uint32_t)((l >> 4) & 1) * 16;
        const uint32_t bLane = bufb + BOFF + (uint32_t)(l & 15) * 272
                             + (uint32_t)((l >> 4) & 1) * 16
                             + (uint32_t)(wc * 32) * 2;
        #pragma unroll
        for (int ks = 0; ks < 4; ks++) {
            uint32_t af[4][4], bf[2][4];
            #pragma unroll
            for (int mf = 0; mf < 4; mf++)
                ldsm_x4(af[mf], aLane + (uint32_t)mf * 2304 + (uint32_t)ks * 32);
            #pragma unroll
            for (int p = 0; p < 2; p++)
                ldsm_x4_trans(bf[p], bLane + (uint32_t)ks * 4352 + (uint32_t)p * 32);
            #pragma unroll
            for (int mf = 0; mf < 4; mf++)
                #pragma unroll
                for (int nf = 0; nf < 4; nf++)
                    mma16816h(acc[mf][nf], af[mf], &bf[nf >> 1][(nf & 1) * 2]);
        }
    };

    fillA(0, sb); fillB(0, sb);
    __syncthreads();
    #pragma unroll
    for (int c = 0; c < NC; c++) {
        uint32_t cur = sb + (uint32_t)(c & 1) * BUF;
        if (c + 1 < NC) {
            uint32_t nxt = sb + (uint32_t)((c + 1) & 1) * BUF;
            fillA(c + 1, nxt); fillB(c + 1, nxt);
        }
        compute(cur);
        __syncthreads();
    }

    #pragma unroll
    for (int mf = 0; mf < 4; mf++) {
        int r0 = m0 + wr * 64 + mf * 16 + (l >> 2);
        #pragma unroll
        for (int nf = 0; nf < 4; nf++) {
            int colL = wc * 32 + nf * 8 + (l & 3) * 2;
            int gc = z * 128 + colL;
            bool selL = gc < NHALF;
            int ch = selL ? gc : gc - NHALF;
            if (r0 < M) {
                if (selL)
                    *(__half2*)(Hl + (size_t)r0 * NHALF + ch) =
                        __floats2half2_rn(acc[mf][nf][0], acc[mf][nf][1]);
                else
                    *(float2*)(Cr + (size_t)r0 * NHALF + ch) =
                        make_float2(acc[mf][nf][0], acc[mf][nf][1]);
            }
            if (r0 + 8 < M) {
                if (selL)
                    *(__half2*)(Hl + (size_t)(r0 + 8) * NHALF + ch) =
                        __floats2half2_rn(acc[mf][nf][2], acc[mf][nf][3]);
                else
                    *(float2*)(Cr + (size_t)(r0 + 8) * NHALF + ch) =
                        make_float2(acc[mf][nf][2], acc[mf][nf][3]);
            }
        }
    }
}

// ==================== CSR build ==============================================
__global__ void zero_deg_kernel() {
    int i = blockIdx.x * blockDim.x + threadIdx.x;
    if (i < N_NODES) g_deg[i] = 0;
}

__global__ void scan_kernel(int E) {
    __shared__ int wsums[32];
    __shared__ int carry_sh;
    const int lane = threadIdx.x & 31;
    const int w    = threadIdx.x >> 5;
    if (threadIdx.x == 0) carry_sh = 0;
    __syncthreads();
    for (int base = 0; base < N_NODES; base += 1024) {
        int i = base + (int)threadIdx.x;
        int v = (i < N_NODES) ? g_deg[i] : 0;
        int x = v;
        #pragma unroll
        for (int o = 1; o < 32; o <<= 1) {
            int t = __shfl_up_sync(0xFFFFFFFFu, x, o);
            if (lane >= o) x += t;
        }
        if (lane == 31) wsums[w] = x;
        __syncthreads();
        if (w == 0) {
            int y = wsums[lane];
            #pragma unroll
            for (int o = 1; o < 32; o <<= 1) {
                int u = __shfl_up_sync(0xFFFFFFFFu, y, o);
                if (lane >= o) y += u;
            }
            wsums[lane] = y;
        }
        __syncthreads();
        int warpoff = (w == 0) ? 0 : wsums[w - 1];
        int incl = x + warpoff + carry_sh;
        if (i < N_NODES) { g_rowptr[i] = incl - v; g_wp[i] = incl - v; }
        __syncthreads();
        if (threadIdx.x == 1023) carry_sh = incl;
        __syncthreads();
    }
    if (threadIdx.x == 0) g_rowptr[N_NODES] = E;
}

__global__ void scatter_kernel(const int* __restrict__ src, const int* __restrict__ dst, int E) {
    int i = (blockIdx.x * blockDim.x + threadIdx.x) * 4;
    if (i >= E) return;
    if (i + 4 <= E) {
        int4 s = *(const int4*)(src + i);
        int4 d = *(const int4*)(dst + i);
        int p0 = atomicAdd(&g_wp[d.x], 1);
        int p1 = atomicAdd(&g_wp[d.y], 1);
        int p2 = atomicAdd(&g_wp[d.z], 1);
        int p3 = atomicAdd(&g_wp[d.w], 1);
        g_csrc[p0] = s.x; g_csrc[p1] = s.y; g_csrc[p2] = s.z; g_csrc[p3] = s.w;
    } else {
        for (int e = i; e < E; e++) {
            int pos = atomicAdd(&g_wp[dst[e]], 1);
            g_csrc[pos] = src[e];
        }
    }
}

// ==================== fused GATv2 edge phase ==================================
// Sub-warp groups: F/8 lanes per edge, 8 features per lane (uint4 load),
// 2 edges in flight per group (R7 configuration — measured best).
template<int F, bool RELU>
__global__ void gat_aggregate_kernel(const __half* __restrict__ xl,
                                     const float* __restrict__ xr,
                                     const float* __restrict__ att,
                                     const float* __restrict__ bias,
                                     float* __restrict__ out) {
    constexpr int GS = F / 8;
    constexpr int NG = 32 / GS;
    int n    = (blockIdx.x * blockDim.x + threadIdx.x) >> 5;
    int lane = threadIdx.x & 31;
    if (n >= N_NODES) return;
    const int gid = lane / GS;
    const int f0  = (lane % GS) * 8;

    float xrv[8], attv[8], acc[8];
    {
        float4 xa = *(const float4*)(xr + (size_t)n * F + f0);
        float4 xb = *(const float4*)(xr + (size_t)n * F + f0 + 4);
        float4 aa = *(const float4*)(att + f0);
        float4 ab = *(const float4*)(att + f0 + 4);
        xrv[0]=xa.x; xrv[1]=xa.y; xrv[2]=xa.z; xrv[3]=xa.w;
        xrv[4]=xb.x; xrv[5]=xb.y; xrv[6]=xb.z; xrv[7]=xb.w;
        attv[0]=aa.x; attv[1]=aa.y; attv[2]=aa.z; attv[3]=aa.w;
        attv[4]=ab.x; attv[5]=ab.y; attv[6]=ab.z; attv[7]=ab.w;
    }
    #pragma unroll
    for (int k = 0; k < 8; k++) acc[k] = 0.0f;
    float s = 0.0f;

    const int start = g_rowptr[n];
    const int end   = g_rowptr[n + 1];

    auto unpack = [](uint4 u, float* v) {
        float2 a = __half22float2(*(const __half2*)&u.x);
        float2 b = __half22float2(*(const __half2*)&u.y);
        float2 c = __half22float2(*(const __half2*)&u.z);
        float2 d = __half22float2(*(const __half2*)&u.w);
        v[0] = a.x; v[1] = a.y; v[2] = b.x; v[3] = b.y;
        v[4] = c.x; v[5] = c.y; v[6] = d.x; v[7] = d.y;
    };

    for (int base = start; base < end; base += 32) {
        int myid = (base + lane < end) ? g_csrc[base + lane] : 0;
        int cnt  = min(32, end - base);
        for (int j = 0; j < cnt; j += 2 * NG) {
            int i0 = j + 2 * gid;
            int i1 = i0 + 1;
            int sn0 = __shfl_sync(0xFFFFFFFFu, myid, min(i0, cnt - 1));
            int sn1 = __shfl_sync(0xFFFFFFFFu, myid, min(i1, cnt - 1));
            bool a0 = i0 < cnt, a1 = i1 < cnt;
            uint4 u0 = *(const uint4*)(xl + (size_t)sn0 * F + f0);
            uint4 u1 = *(const uint4*)(xl + (size_t)sn1 * F + f0);
            float v0[8], v1[8];
            unpack(u0, v0);
            unpack(u1, v1);
            float p0 = 0.0f, p1 = 0.0f;
            #pragma unroll
            for (int k = 0; k < 8; k++) {
                float z0 = v0[k] + xrv[k];
                float z1 = v1[k] + xrv[k];
                float lz0 = z0 > 0.0f ? z0 : NEG_SLOPE * z0;
                float lz1 = z1 > 0.0f ? z1 : NEG_SLOPE * z1;
                p0 = fmaf(attv[k], lz0, p0);
                p1 = fmaf(attv[k], lz1, p1);
            }
            #pragma unroll
            for (int o = GS / 2; o > 0; o >>= 1) {
                p0 += __shfl_xor_sync(0xFFFFFFFFu, p0, o);
                p1 += __shfl_xor_sync(0xFFFFFFFFu, p1, o);
            }
            float e0 = a0 ? __expf(p0) : 0.0f;
            float e1 = a1 ? __expf(p1) : 0.0f;
            s += e0 + e1;
            #pragma unroll
            for (int k = 0; k < 8; k++)
                acc[k] = fmaf(e0, v0[k], fmaf(e1, v1[k], acc[k]));
        }
    }

    #pragma unroll
    for (int o = GS; o < 32; o <<= 1) {
        s += __shfl_xor_sync(0xFFFFFFFFu, s, o);
        #pragma unroll
        for (int k = 0; k < 8; k++)
            acc[k] += __shfl_xor_sync(0xFFFFFFFFu, acc[k], o);
    }

    if (gid == 0) {
        float inv = 1.0f / (s + EPS_F);
        float4 ba = *(const float4*)(bias + f0);
        float4 bb = *(const float4*)(bias + f0 + 4);
        float bv[8] = {ba.x, ba.y, ba.z, ba.w, bb.x, bb.y, bb.z, bb.w};
        float o0[8];
        #pragma unroll
        for (int k = 0; k < 8; k++) {
            float v = acc[k] * inv + bv[k];
            o0[k] = RELU ? (v > 0.0f ? v : 0.0f) : v;
        }
        float* dp = out + (size_t)n * F + f0;
        *(float4*)(dp)     = make_float4(o0[0], o0[1], o0[2], o0[3]);
        *(float4*)(dp + 4) = make_float4(o0[4], o0[5], o0[6], o0[7]);
    }
}

// ==================== launch =================================================
extern "C" void kernel_launch(void* const* d_in, const int* in_sizes, int n_in,
                              void* d_out, int out_size) {
    const float* x    = (const float*)d_in[0];
    const int*   ei   = (const int*)  d_in[1];
    const float* Wl1  = (const float*)d_in[2];
    const float* Wr1  = (const float*)d_in[3];
    const float* att1 = (const float*)d_in[4];
    const float* b1   = (const float*)d_in[5];
    const float* Wl2  = (const float*)d_in[6];
    const float* Wr2  = (const float*)d_in[7];
    const float* att2 = (const float*)d_in[8];
    const float* b2   = (const float*)d_in[9];
    float* out = (float*)d_out;

    const int E = in_sizes[1] / 2;
    const int* src = ei;
    const int* dst = ei + E;

    __half *p_xl1h, *p_xl2h;
    float *p_xr1, *p_h, *p_xr2;
    cudaGetSymbolAddress((void**)&p_xl1h, g_xl1h);
    cudaGetSymbolAddress((void**)&p_xr1,  g_xr1);
    cudaGetSymbolAddress((void**)&p_h,    g_h);
    cudaGetSymbolAddress((void**)&p_xl2h, g_xl2h);
    cudaGetSymbolAddress((void**)&p_xr2,  g_xr2);

    const int SMEM = 2 * 35840;
    cudaFuncSetAttribute(gemm_mma_fp16<F_IN,  H_DIM, true>,
                         cudaFuncAttributeMaxDynamicSharedMemorySize, SMEM);
    cudaFuncSetAttribute(gemm_mma_fp16<H_DIM, C_DIM, false>,
                         cudaFuncAttributeMaxDynamicSharedMemorySize, SMEM);

    const int TILES = (N_NODES + 127) / 128;
    const int Q4 = (E + 3) / 4;

    // ---- CSR degree zero, then GEMM1 with fused histogram (z==2) ----
    zero_deg_kernel<<<(N_NODES + 255) / 256, 256>>>();
    {
        dim3 grid(TILES, 1, 3);   // z=0,1: GEMM halves; z=2: histogram
        gemm_mma_fp16<F_IN, H_DIM, true><<<grid, 256, SMEM>>>(
            x, Wl1, Wr1, p_xl1h, p_xr1, N_NODES, dst, E);
    }
    scan_kernel<<<1, 1024>>>(E);
    scatter_kernel<<<(Q4 + 255) / 256, 256>>>(src, dst, E);

    // ---- layer 1 aggregate ----
    gat_aggregate_kernel<128, true><<<(N_NODES + 7) / 8, 256>>>(
        p_xl1h, p_xr1, att1, b1, p_h);

    // ---- layer 2 ----
    {
        dim3 grid(TILES, 1, 1);
        gemm_mma_fp16<H_DIM, C_DIM, false><<<grid, 256, SMEM>>>(
            p_h, Wl2, Wr2, p_xl2h, p_xr2, N_NODES, nullptr, 0);
    }
    gat_aggregate_kernel<64, false><<<(N_NODES + 7) / 8, 256>>>(
        p_xl2h, p_xr2, att2, b2, out);
}